// round 14
// baseline (speedup 1.0000x reference)
#include <cuda_runtime.h>
#include <cuda_fp16.h>
#include <cstdint>

#define BATCH 8
#define CH 256
#define HH 56
#define WW 56
#define HWSZ 3136
#define NPIX 25088     // 196 * 128
#define EPSBN 1e-5f
#define PITCH 48       // smem row pitch (bytes): conflict-free ldmatrix

typedef unsigned int u32;

// ---------------- device scratch ----------------
static __device__ __half g_xh[NPIX * CH];        // x NHWC fp16
static __device__ __half g_o1h[NPIX * CH];       // out1 fp16 (NHWC)
static __device__ float  g_offs[NPIX * 18];
static __device__ __half g_w1h[9 * CH * CH];     // [k][oc][c] fp16
static __device__ __half g_w2h[9 * CH * CH];
static __device__ __half g_woh[9 * 32 * CH];     // [k][oc32][c]

// ---------------- helpers ----------------
__device__ __forceinline__ u32 smem_u32(const void* p) {
    u32 a;
    asm("{ .reg .u64 t; cvta.to.shared.u64 t, %1; cvt.u32.u64 %0, t; }" : "=r"(a) : "l"(p));
    return a;
}
__device__ __forceinline__ void ldm4(u32 addr, u32* r) {
    asm volatile("ldmatrix.sync.aligned.m8n8.x4.shared.b16 {%0,%1,%2,%3}, [%4];"
                 : "=r"(r[0]), "=r"(r[1]), "=r"(r[2]), "=r"(r[3]) : "r"(addr));
}
__device__ __forceinline__ void mma_f16(float* c, const u32* a, u32 b0, u32 b1) {
    asm volatile(
        "mma.sync.aligned.m16n8k16.row.col.f32.f16.f16.f32 "
        "{%0,%1,%2,%3}, {%4,%5,%6,%7}, {%8,%9}, {%0,%1,%2,%3};"
        : "+f"(c[0]), "+f"(c[1]), "+f"(c[2]), "+f"(c[3])
        : "r"(a[0]), "r"(a[1]), "r"(a[2]), "r"(a[3]), "r"(b0), "r"(b1));
}
__device__ __forceinline__ void cpa16(u32 dst, const void* src, u32 sz) {
    asm volatile("cp.async.cg.shared.global [%0], [%1], 16, %2;"
                 :: "r"(dst), "l"(src), "r"(sz) : "memory");
}
__device__ __forceinline__ void cpa16ca(u32 dst, const void* src) {
    asm volatile("cp.async.ca.shared.global [%0], [%1], 16;"
                 :: "r"(dst), "l"(src) : "memory");
}
#define CPCOMMIT() asm volatile("cp.async.commit_group;" ::: "memory")
#define CPWAIT1()  asm volatile("cp.async.wait_group 1;" ::: "memory")
#define CPWAIT2()  asm volatile("cp.async.wait_group 2;" ::: "memory")

// ---------------- prep kernels ----------------
__global__ void prep_x(const float* __restrict__ x) {
    __shared__ float tile[32][33];
    const int b = blockIdx.z, hw0 = blockIdx.x * 32, c0 = blockIdx.y * 32;
    const int tx = threadIdx.x, ty = threadIdx.y;
#pragma unroll
    for (int j = 0; j < 4; ++j)
        tile[ty + j * 8][tx] = x[(b * CH + c0 + ty + j * 8) * HWSZ + hw0 + tx];
    __syncthreads();
#pragma unroll
    for (int j = 0; j < 4; ++j) {
        const float v = tile[tx][ty + j * 8];
        const int pix = b * HWSZ + hw0 + ty + j * 8;
        g_xh[pix * CH + c0 + tx] = __float2half(v);
    }
}

__global__ void prep_w(const float* __restrict__ w, int which) {
    const int idx = blockIdx.x * 256 + threadIdx.x;   // 9*256*256
    const int k = idx >> 16, r = idx & 65535, oc = r >> 8, c = r & 255;
    const float v = w[(oc * CH + c) * 9 + k];
    const int o = (k * CH + oc) * CH + c;
    if (which) g_w2h[o] = __float2half(v); else g_w1h[o] = __float2half(v);
}

__global__ void prep_woff(const float* __restrict__ w) {
    const int idx = blockIdx.x * 256 + threadIdx.x;   // 9*32*256
    const int k = idx >> 13, r = idx & 8191, oc = r >> 8, c = r & 255;
    const float v = (oc < 18) ? w[(oc * CH + c) * 9 + k] : 0.f;
    g_woh[(k * 32 + oc) * CH + c] = __float2half(v);
}

// ================= conv1: 64px x 128oc per CTA, BK=32, 3-stage =================
// half (9216): A 0 (3072), B 3072 (6144); stage = 2 halves = 18432
#define C1_HALF 9216
#define C1_ST   18432
#define C1_IB   55296
#define C1_SZ   57344
#define NIT32   72

__global__ __launch_bounds__(128, 3)
void conv1_mma(const float* __restrict__ bg, const float* __restrict__ bb_,
               const float* __restrict__ bm, const float* __restrict__ bv) {
    extern __shared__ __align__(16) char S[];
    const int tid = threadIdx.x, lane = tid & 31, wid = tid >> 5;
    const int pixbase = blockIdx.x * 64, octile = blockIdx.y * 128;
    const u32 sb = smem_u32(S);
    float* invbet = (float*)(S + C1_IB);
    {
        const float iv0 = bg[tid] * rsqrtf(bv[tid] + EPSBN);
        invbet[tid] = iv0;
        invbet[256 + tid] = bb_[tid] - bm[tid] * iv0;
        const float iv1 = bg[tid + 128] * rsqrtf(bv[tid + 128] + EPSBN);
        invbet[tid + 128] = iv1;
        invbet[256 + tid + 128] = bb_[tid + 128] - bm[tid + 128] * iv1;
    }

    const int rowA = tid >> 1, chA = tid & 1;
    const int gp = pixbase + rowA;
    const int bIdx = gp / HWSZ, rem = gp - bIdx * HWSZ;
    const int py = rem / WW, px = rem - (rem / WW) * WW;
    const int pixrowbase = bIdx * HWSZ;
    const u32 dstA = (u32)(rowA * PITCH + chA * 16);
    const int rowB = tid >> 1, chB = tid & 1;
    const u32 dstB = 3072u + (u32)(rowB * PITCH + chB * 16);

    auto LOADC = [&](int i, int s) {
        const int k = i >> 3, c0 = (i & 7) << 5;
        const int ky = k / 3, kx = k - (k / 3) * 3;
        const int sy = py + ky - 1, sx = px + kx - 1;
        const bool v = ((unsigned)sy < HH) & ((unsigned)sx < WW);
        const int ga0 = ((pixrowbase + sy * WW + sx) << 8) + chA * 8;
        const int gb0 = ((k * CH + octile + rowB) << 8) + chB * 8;
#pragma unroll
        for (int h = 0; h < 2; ++h) {
            const int ch = c0 + h * 16;
            const u32 base = sb + s * C1_ST + h * C1_HALF;
            cpa16(base + dstA, v ? (const void*)(g_xh + ga0 + ch) : (const void*)g_xh, v ? 16u : 0u);
            const int w0 = gb0 + ch, w1 = w0 + (64 << 8);
            cpa16ca(base + dstB,        g_w1h + w0);
            cpa16ca(base + 3072 + dstB, g_w1h + w1);
        }
    };

    const int wn = wid & 3;
    const u32 aoff = (u32)((lane & 15) * PITCH + (lane >> 4) * 16);
    const u32 boff = 3072u + (u32)((wn * 32 + ((lane >> 4) << 3) + (lane & 7)) * PITCH +
                                   ((lane >> 3) & 1) * 16);
    float acc[4][4][4];
#pragma unroll
    for (int a = 0; a < 4; ++a)
#pragma unroll
        for (int b = 0; b < 4; ++b)
#pragma unroll
            for (int c = 0; c < 4; ++c) acc[a][b][c] = 0.f;

    auto COMP = [&](int s) {
#pragma unroll
        for (int h = 0; h < 2; ++h) {
            const u32 sub = sb + s * C1_ST + h * C1_HALF;
            const u32 ab = sub + aoff;
            const u32 bbx = sub + boff;
            u32 bh0[4], bh1[4];
            ldm4(bbx, bh0); ldm4(bbx + 768, bh1);
            u32 ah[2][4];
            ldm4(ab, ah[0]);
#pragma unroll
            for (int mt = 0; mt < 4; ++mt) {
                const int cur = mt & 1, nxt = cur ^ 1;
                if (mt < 3) ldm4(ab + (mt + 1) * 768, ah[nxt]);
#pragma unroll
                for (int nt = 0; nt < 4; ++nt) {
                    u32* bq = (nt < 2) ? bh0 : bh1; const int hh = (nt & 1) * 2;
                    mma_f16(acc[mt][nt], ah[cur], bq[hh], bq[hh + 1]);
                }
            }
        }
    };

    LOADC(0, 0); CPCOMMIT();
    LOADC(1, 1); CPCOMMIT();
    for (int i = 0; i < NIT32; ++i) {
        CPWAIT1();                 // group i complete
        __syncthreads();
        if (i + 2 < NIT32) LOADC(i + 2, (i + 2) % 3);  // stage (i-1)%3: reads done pre-sync
        CPCOMMIT();
        COMP(i % 3);
    }

    const int g = lane >> 2, t2 = (lane & 3) * 2;
#pragma unroll
    for (int mt = 0; mt < 4; ++mt) {
        const int pr = pixbase + mt * 16 + g;
#pragma unroll
        for (int nt = 0; nt < 4; ++nt) {
            const int oc = octile + wn * 32 + nt * 8 + t2;
            const float i0 = invbet[oc], i1 = invbet[oc + 1];
            const float e0 = invbet[256 + oc], e1 = invbet[256 + oc + 1];
            const float v00 = fmaxf(fmaf(acc[mt][nt][0], i0, e0), 0.f);
            const float v01 = fmaxf(fmaf(acc[mt][nt][1], i1, e1), 0.f);
            const float v10 = fmaxf(fmaf(acc[mt][nt][2], i0, e0), 0.f);
            const float v11 = fmaxf(fmaf(acc[mt][nt][3], i1, e1), 0.f);
            __half2 th;
            th.x = __float2half(v00); th.y = __float2half(v01);
            *(__half2*)(g_o1h + pr * CH + oc) = th;
            th.x = __float2half(v10); th.y = __float2half(v11);
            *(__half2*)(g_o1h + (pr + 8) * CH + oc) = th;
        }
    }
}

// ================= offset conv: 128px x 32oc, BK=32, 4-stage =================
// half (7680): A 0 (6144), B 6144 (1536); stage = 15360
#define OF_HALF 7680
#define OF_ST   15360
#define OF_OB   61440
#define OF_SZ   61568

__global__ __launch_bounds__(256, 2)
void convoff_mma(const float* __restrict__ offb) {
    extern __shared__ __align__(16) char S[];
    const int tid = threadIdx.x, lane = tid & 31, wid = tid >> 5;
    const int pixbase = blockIdx.x * 128;
    const u32 sb = smem_u32(S);
    float* obs = (float*)(S + OF_OB);
    if (tid < 32) obs[tid] = (tid < 18) ? offb[tid] : 0.f;

    const int rowA = tid >> 1, chA = tid & 1;
    const int gp = pixbase + rowA;
    const int bIdx = gp / HWSZ, rem = gp - bIdx * HWSZ;
    const int py = rem / WW, px = rem - (rem / WW) * WW;
    const int pixrowbase = bIdx * HWSZ;
    const u32 dstA = (u32)(rowA * PITCH + chA * 16);
    const int rowB = (tid >> 1) & 31, chB = tid & 1;   // valid for tid<64
    const u32 dstB = 6144u + (u32)(rowB * PITCH + chB * 16);

    auto LOADC = [&](int i, int s) {
        const int k = i >> 3, c0 = (i & 7) << 5;
        const int ky = k / 3, kx = k - (k / 3) * 3;
        const int sy = py + ky - 1, sx = px + kx - 1;
        const bool v = ((unsigned)sy < HH) & ((unsigned)sx < WW);
        const int ga0 = ((pixrowbase + sy * WW + sx) << 8) + chA * 8;
#pragma unroll
        for (int h = 0; h < 2; ++h) {
            const int ch = c0 + h * 16;
            const u32 base = sb + s * OF_ST + h * OF_HALF;
            cpa16(base + dstA, v ? (const void*)(g_o1h + ga0 + ch) : (const void*)g_o1h, v ? 16u : 0u);
            if (tid < 64) {
                const int gb = ((k * 32 + rowB) << 8) + ch + chB * 8;
                cpa16ca(base + dstB, g_woh + gb);
            }
        }
    };

    const int wm = wid >> 1, wn = wid & 1;
    const u32 aoff = (u32)((wm * 32 + (lane & 15)) * PITCH + (lane >> 4) * 16);
    const u32 boff = 6144u + (u32)((wn * 16 + ((lane >> 4) << 3) + (lane & 7)) * PITCH +
                                   ((lane >> 3) & 1) * 16);
    float acc[2][2][4];
#pragma unroll
    for (int a = 0; a < 2; ++a)
#pragma unroll
        for (int b = 0; b < 2; ++b)
#pragma unroll
            for (int c = 0; c < 4; ++c) acc[a][b][c] = 0.f;

    auto COMP = [&](int s) {
#pragma unroll
        for (int h = 0; h < 2; ++h) {
            const u32 sub = sb + s * OF_ST + h * OF_HALF;
            const u32 ab = sub + aoff;
            const u32 bbx = sub + boff;
            u32 bh[4];
            ldm4(bbx, bh);
            u32 ah[2][4];
            ldm4(ab, ah[0]);
            ldm4(ab + 768, ah[1]);
#pragma unroll
            for (int mt = 0; mt < 2; ++mt)
#pragma unroll
                for (int nt = 0; nt < 2; ++nt)
                    mma_f16(acc[mt][nt], ah[mt], bh[nt * 2], bh[nt * 2 + 1]);
        }
    };

    LOADC(0, 0); CPCOMMIT();
    LOADC(1, 1); CPCOMMIT();
    LOADC(2, 2); CPCOMMIT();
    for (int i = 0; i < NIT32; ++i) {
        CPWAIT2();
        __syncthreads();
        if (i + 3 < NIT32) LOADC(i + 3, (i + 3) & 3);
        CPCOMMIT();
        COMP(i & 3);
    }

    const int g = lane >> 2, t2 = (lane & 3) * 2;
#pragma unroll
    for (int mt = 0; mt < 2; ++mt) {
        const int pr = pixbase + wm * 32 + mt * 16 + g;
#pragma unroll
        for (int nt = 0; nt < 2; ++nt) {
            const int oc = wn * 16 + nt * 8 + t2;
            if (oc < 18) {
                g_offs[pr * 18 + oc] = acc[mt][nt][0] + obs[oc];
                g_offs[(pr + 8) * 18 + oc] = acc[mt][nt][2] + obs[oc];
            }
            if (oc + 1 < 18) {
                g_offs[pr * 18 + oc + 1] = acc[mt][nt][1] + obs[oc + 1];
                g_offs[(pr + 8) * 18 + oc + 1] = acc[mt][nt][3] + obs[oc + 1];
            }
        }
    }
}

// ================= deformable conv: 64px x 128oc per CTA =================
// A: 2 stages x 3072; B: 3 stages x 6144 at 6144; fp16 gather; B via L1
#define DF_AST 3072
#define DF_B0  6144
#define DF_IB  24576
#define DF_CW  26624
#define DF_PK  35840
#define DF_SZ  38400
#define NITER  144

__global__ __launch_bounds__(128, 3)
void deform_mma(const float* __restrict__ bg, const float* __restrict__ bb_,
                const float* __restrict__ bm, const float* __restrict__ bv,
                const float* __restrict__ resid, float* __restrict__ out) {
    extern __shared__ __align__(16) char S[];
    const int tid = threadIdx.x, lane = tid & 31, wid = tid >> 5;
    const int pixbase = blockIdx.x * 64, octile = blockIdx.y * 128;
    const u32 sb = smem_u32(S);
    float*  invbet = (float*)(S + DF_IB);
    float4* cwS = (float4*)(S + DF_CW);
    int*    cpkS = (int*)(S + DF_PK);
    {
        const float iv0 = bg[tid] * rsqrtf(bv[tid] + EPSBN);
        invbet[tid] = iv0;
        invbet[256 + tid] = bb_[tid] - bm[tid] * iv0;
        const float iv1 = bg[tid + 128] * rsqrtf(bv[tid + 128] + EPSBN);
        invbet[tid + 128] = iv1;
        invbet[256 + tid + 128] = bb_[tid + 128] - bm[tid + 128] * iv1;
    }
    for (int idx = tid; idx < 64 * 9; idx += 128) {
        const int p = idx / 9, k = idx - (idx / 9) * 9;
        const int gpq = pixbase + p;
        const int b = gpq / HWSZ, rm = gpq - b * HWSZ;
        const int yy = rm / WW, xx = rm - (rm / WW) * WW;
        const float oy = g_offs[gpq * 18 + k];
        const float ox = g_offs[gpq * 18 + 9 + k];
        const float ys = (float)(yy + k / 3 - 1) + oy;
        const float xs = (float)(xx + (k - (k / 3) * 3) - 1) + ox;
        const float yf = floorf(ys), xf = floorf(xs);
        const float ty = ys - yf, tx = xs - xf;
        const int iy0 = (int)yf, ix0 = (int)xf;
        const int iy1 = iy0 + 1, ix1 = ix0 + 1;
        const float vy0 = ((unsigned)iy0 < HH) ? 1.f : 0.f;
        const float vy1 = ((unsigned)iy1 < HH) ? 1.f : 0.f;
        const float vx0 = ((unsigned)ix0 < WW) ? 1.f : 0.f;
        const float vx1 = ((unsigned)ix1 < WW) ? 1.f : 0.f;
        cwS[idx] = make_float4((1.f - ty) * (1.f - tx) * vy0 * vx0,
                               (1.f - ty) * tx * vy0 * vx1,
                               ty * (1.f - tx) * vy1 * vx0,
                               ty * tx * vy1 * vx1);
        const int cy0 = min(max(iy0, 0), HH - 1), cy1 = min(max(iy1, 0), HH - 1);
        const int cx0 = min(max(ix0, 0), WW - 1), cx1 = min(max(ix1, 0), WW - 1);
        cpkS[idx] = cy0 | (cx0 << 8) | (cy1 << 16) | (cx1 << 24);
    }
    __syncthreads();

    const int rowA = tid >> 1, chA = tid & 1;
    const int gp = pixbase + rowA;
    const int pixrowbase = (gp / HWSZ) * HWSZ;
    const u32 dstA = (u32)(rowA * PITCH + chA * 16);
    const int rowB = tid >> 1, chB = tid & 1;
    const u32 dstB = (u32)(rowB * PITCH + chB * 16);

    uint4 cr[4];     // fp16 gather: 8 ch x 4 corners
    float4 wreg;

    auto LDGA = [&](int i) {
        const int k = i >> 4, c0 = (i & 15) << 4;
        wreg = cwS[rowA * 9 + k];
        const int pk = cpkS[rowA * 9 + k];
        const int cc = c0 + chA * 8;
        const int r00 = ((pixrowbase + (pk & 255) * WW + ((pk >> 8) & 255)) << 8) + cc;
        const int r01 = ((pixrowbase + (pk & 255) * WW + ((pk >> 24) & 255)) << 8) + cc;
        const int r10 = ((pixrowbase + ((pk >> 16) & 255) * WW + ((pk >> 8) & 255)) << 8) + cc;
        const int r11 = ((pixrowbase + ((pk >> 16) & 255) * WW + ((pk >> 24) & 255)) << 8) + cc;
        cr[0] = *(const uint4*)(g_o1h + r00);
        cr[1] = *(const uint4*)(g_o1h + r01);
        cr[2] = *(const uint4*)(g_o1h + r10);
        cr[3] = *(const uint4*)(g_o1h + r11);
    };
    auto STSA = [&](int s) {
        __align__(16) __half hh[8];
        const __half2* c00 = (const __half2*)&cr[0];
        const __half2* c01 = (const __half2*)&cr[1];
        const __half2* c10 = (const __half2*)&cr[2];
        const __half2* c11 = (const __half2*)&cr[3];
#pragma unroll
        for (int q = 0; q < 4; ++q) {
            const float2 s00 = __half22float2(c00[q]);
            const float2 s01 = __half22float2(c01[q]);
            const float2 s10 = __half22float2(c10[q]);
            const float2 s11 = __half22float2(c11[q]);
            float vx, vy;
            vx = fmaf(wreg.x, s00.x, fmaf(wreg.y, s01.x, fmaf(wreg.z, s10.x, wreg.w * s11.x)));
            vy = fmaf(wreg.x, s00.y, fmaf(wreg.y, s01.y, fmaf(wreg.z, s10.y, wreg.w * s11.y)));
            hh[q * 2 + 0] = __float2half(vx);
            hh[q * 2 + 1] = __float2half(vy);
        }
        *(uint4*)(S + s * DF_AST + dstA) = *(uint4*)hh;
    };
    auto CPB = [&](int i, int s) {
        const int k = i >> 4, c0 = (i & 15) << 4;
        const int gb0 = ((k * CH + octile + rowB) << 8) + c0 + chB * 8;
        const int gb1 = gb0 + (64 << 8);
        const u32 base = sb + DF_B0 + s * 6144;
        cpa16ca(base + dstB,        g_w2h + gb0);
        cpa16ca(base + 3072 + dstB, g_w2h + gb1);
    };

    const int wn = wid & 3;
    const u32 aoff = (u32)((lane & 15) * PITCH + (lane >> 4) * 16);
    const u32 boff = (u32)((wn * 32 + ((lane >> 4) << 3) + (lane & 7)) * PITCH +
                           ((lane >> 3) & 1) * 16);
    float acc[4][4][4];
#pragma unroll
    for (int a = 0; a < 4; ++a)
#pragma unroll
        for (int b = 0; b < 4; ++b)
#pragma unroll
            for (int c = 0; c < 4; ++c) acc[a][b][c] = 0.f;

    auto COMP = [&](int sa, int sbst) {
        const u32 ab = sb + sa * DF_AST + aoff;
        const u32 bbx = sb + DF_B0 + sbst * 6144 + boff;
        u32 bh0[4], bh1[4];
        ldm4(bbx, bh0); ldm4(bbx + 768, bh1);
        u32 ah[2][4];
        ldm4(ab, ah[0]);
#pragma unroll
        for (int mt = 0; mt < 4; ++mt) {
            const int cur = mt & 1, nxt = cur ^ 1;
            if (mt < 3) ldm4(ab + (mt + 1) * 768, ah[nxt]);
#pragma unroll
            for (int nt = 0; nt < 4; ++nt) {
                u32* bq = (nt < 2) ? bh0 : bh1; const int h = (nt & 1) * 2;
                mma_f16(acc[mt][nt], ah[cur], bq[h], bq[h + 1]);
            }
        }
    };

    LDGA(0); STSA(0);
    CPB(0, 0); CPCOMMIT();
    CPB(1, 1); CPCOMMIT();
    __syncthreads();

    for (int i = 0; i < NITER; ++i) {
        CPWAIT1();                 // B group i arrived
        __syncthreads();           // STSA(i) + B(i) visible
        if (i + 2 < NITER) CPB(i + 2, (i + 2) % 3);   // stage (i-1)%3
        CPCOMMIT();
        if (i + 1 < NITER) LDGA(i + 1);
        COMP(i & 1, i % 3);
        if (i + 1 < NITER) STSA((i + 1) & 1);
    }

    const int g = lane >> 2, t2 = (lane & 3) * 2;
#pragma unroll
    for (int mt = 0; mt < 4; ++mt) {
        const int pr0 = pixbase + mt * 16 + g;
        const int pr1 = pr0 + 8;
        const int b0 = pr0 / HWSZ, rm0 = pr0 - b0 * HWSZ;
        const int b1 = pr1 / HWSZ, rm1 = pr1 - b1 * HWSZ;
        const int base0 = b0 * (CH * HWSZ) + rm0;
        const int base1 = b1 * (CH * HWSZ) + rm1;
#pragma unroll
        for (int nt = 0; nt < 4; ++nt) {
            const int oc = octile + wn * 32 + nt * 8 + t2;
            const float i0 = invbet[oc], i1 = invbet[oc + 1];
            const float e0 = invbet[256 + oc], e1 = invbet[256 + oc + 1];
            const int a00 = base0 + oc * HWSZ, a01 = a00 + HWSZ;
            const int a10 = base1 + oc * HWSZ, a11 = a10 + HWSZ;
            out[a00] = fmaxf(fmaf(acc[mt][nt][0], i0, e0) + resid[a00], 0.f);
            out[a01] = fmaxf(fmaf(acc[mt][nt][1], i1, e1) + resid[a01], 0.f);
            out[a10] = fmaxf(fmaf(acc[mt][nt][2], i0, e0) + resid[a10], 0.f);
            out[a11] = fmaxf(fmaf(acc[mt][nt][3], i1, e1) + resid[a11], 0.f);
        }
    }
}

// ---------------- launch ----------------
extern "C" void kernel_launch(void* const* d_in, const int* in_sizes, int n_in,
                              void* d_out, int out_size) {
    const float* x    = (const float*)d_in[0];
    const float* w1   = (const float*)d_in[1];
    const float* bn1g = (const float*)d_in[2];
    const float* bn1b = (const float*)d_in[3];
    const float* bn1m = (const float*)d_in[4];
    const float* bn1v = (const float*)d_in[5];
    const float* woff = (const float*)d_in[6];
    const float* offb = (const float*)d_in[7];
    const float* w2   = (const float*)d_in[8];
    const float* bn2g = (const float*)d_in[9];
    const float* bn2b = (const float*)d_in[10];
    const float* bn2m = (const float*)d_in[11];
    const float* bn2v = (const float*)d_in[12];
    float* out = (float*)d_out;

    cudaFuncSetAttribute(conv1_mma,   cudaFuncAttributeMaxDynamicSharedMemorySize, C1_SZ);
    cudaFuncSetAttribute(convoff_mma, cudaFuncAttributeMaxDynamicSharedMemorySize, OF_SZ);
    cudaFuncSetAttribute(deform_mma,  cudaFuncAttributeMaxDynamicSharedMemorySize, DF_SZ);

    prep_x<<<dim3(98, 8, BATCH), dim3(32, 8)>>>(x);
    prep_w<<<2304, 256>>>(w1, 0);
    prep_woff<<<288, 256>>>(woff);
    conv1_mma<<<dim3(392, 2), 128, C1_SZ>>>(bn1g, bn1b, bn1m, bn1v);
    prep_w<<<2304, 256>>>(w2, 1);
    convoff_mma<<<196, 256, OF_SZ>>>(offb);
    deform_mma<<<dim3(392, 2), 128, DF_SZ>>>(bn2g, bn2b, bn2m, bn2v, x, out);
}

// round 15
// speedup vs baseline: 1.0831x; 1.0831x over previous
#include <cuda_runtime.h>
#include <cuda_fp16.h>
#include <cstdint>

#define BATCH 8
#define CH 256
#define HH 56
#define WW 56
#define HWSZ 3136
#define NPIX 25088     // 196 * 128
#define EPSBN 1e-5f
#define PITCH 48       // smem row pitch (bytes): conflict-free ldmatrix

typedef unsigned int u32;

// ---------------- device scratch ----------------
static __device__ __half g_xh[NPIX * CH];        // x NHWC fp16
static __device__ __half g_o1h[NPIX * CH];       // out1 fp16 (NHWC)
static __device__ float  g_offs[NPIX * 18];
static __device__ __half g_w1h[9 * CH * CH];     // [k][oc][c] fp16
static __device__ __half g_w2h[9 * CH * CH];
static __device__ __half g_woh[9 * 32 * CH];     // [k][oc32][c]

// ---------------- helpers ----------------
__device__ __forceinline__ u32 smem_u32(const void* p) {
    u32 a;
    asm("{ .reg .u64 t; cvta.to.shared.u64 t, %1; cvt.u32.u64 %0, t; }" : "=r"(a) : "l"(p));
    return a;
}
__device__ __forceinline__ void ldm4(u32 addr, u32* r) {
    asm volatile("ldmatrix.sync.aligned.m8n8.x4.shared.b16 {%0,%1,%2,%3}, [%4];"
                 : "=r"(r[0]), "=r"(r[1]), "=r"(r[2]), "=r"(r[3]) : "r"(addr));
}
__device__ __forceinline__ void mma_f16(float* c, const u32* a, u32 b0, u32 b1) {
    asm volatile(
        "mma.sync.aligned.m16n8k16.row.col.f32.f16.f16.f32 "
        "{%0,%1,%2,%3}, {%4,%5,%6,%7}, {%8,%9}, {%0,%1,%2,%3};"
        : "+f"(c[0]), "+f"(c[1]), "+f"(c[2]), "+f"(c[3])
        : "r"(a[0]), "r"(a[1]), "r"(a[2]), "r"(a[3]), "r"(b0), "r"(b1));
}
__device__ __forceinline__ void cpa16(u32 dst, const void* src, u32 sz) {
    asm volatile("cp.async.cg.shared.global [%0], [%1], 16, %2;"
                 :: "r"(dst), "l"(src), "r"(sz) : "memory");
}
__device__ __forceinline__ void cpa16ca(u32 dst, const void* src) {
    asm volatile("cp.async.ca.shared.global [%0], [%1], 16;"
                 :: "r"(dst), "l"(src) : "memory");
}
#define CPCOMMIT() asm volatile("cp.async.commit_group;" ::: "memory")
#define CPWAIT1()  asm volatile("cp.async.wait_group 1;" ::: "memory")
#define CPWAIT2()  asm volatile("cp.async.wait_group 2;" ::: "memory")

// ---------------- prep kernels ----------------
__global__ void prep_x(const float* __restrict__ x) {
    __shared__ float tile[32][33];
    const int b = blockIdx.z, hw0 = blockIdx.x * 32, c0 = blockIdx.y * 32;
    const int tx = threadIdx.x, ty = threadIdx.y;
#pragma unroll
    for (int j = 0; j < 4; ++j)
        tile[ty + j * 8][tx] = x[(b * CH + c0 + ty + j * 8) * HWSZ + hw0 + tx];
    __syncthreads();
#pragma unroll
    for (int j = 0; j < 4; ++j) {
        const float v = tile[tx][ty + j * 8];
        const int pix = b * HWSZ + hw0 + ty + j * 8;
        g_xh[pix * CH + c0 + tx] = __float2half(v);
    }
}

__global__ void prep_w(const float* __restrict__ w, int which) {
    const int idx = blockIdx.x * 256 + threadIdx.x;   // 9*256*256
    const int k = idx >> 16, r = idx & 65535, oc = r >> 8, c = r & 255;
    const float v = w[(oc * CH + c) * 9 + k];
    const int o = (k * CH + oc) * CH + c;
    if (which) g_w2h[o] = __float2half(v); else g_w1h[o] = __float2half(v);
}

__global__ void prep_woff(const float* __restrict__ w) {
    const int idx = blockIdx.x * 256 + threadIdx.x;   // 9*32*256
    const int k = idx >> 13, r = idx & 8191, oc = r >> 8, c = r & 255;
    const float v = (oc < 18) ? w[(oc * CH + c) * 9 + k] : 0.f;
    g_woh[(k * 32 + oc) * CH + c] = __float2half(v);
}

// ================= conv1: 128px x 128oc per CTA (256 thr), BK=32, 3-stage =================
// half (12288): A 0 (6144 = 128row x 48), B 6144 (6144 = 128row x 48); stage 24576
#define C1_HALF 12288
#define C1_ST   24576
#define C1_IB   73728
#define C1_SZ   75776
#define NIT32   72

__global__ __launch_bounds__(256, 2)
void conv1_mma(const float* __restrict__ bg, const float* __restrict__ bb_,
               const float* __restrict__ bm, const float* __restrict__ bv) {
    extern __shared__ __align__(16) char S[];
    const int tid = threadIdx.x, lane = tid & 31, wid = tid >> 5;
    const int pixbase = blockIdx.x * 128, octile = blockIdx.y * 128;
    const u32 sb = smem_u32(S);
    float* invbet = (float*)(S + C1_IB);
    {
        const float iv = bg[tid] * rsqrtf(bv[tid] + EPSBN);
        invbet[tid] = iv;
        invbet[256 + tid] = bb_[tid] - bm[tid] * iv;
    }

    const int rowA = tid >> 1, chA = tid & 1;          // 128 rows x 2 chunks
    const int gp = pixbase + rowA;
    const int bIdx = gp / HWSZ, rem = gp - bIdx * HWSZ;
    const int py = rem / WW, px = rem - (rem / WW) * WW;
    const int pixrowbase = bIdx * HWSZ;
    const u32 dstA = (u32)(rowA * PITCH + chA * 16);
    const int rowB = tid >> 1, chB = tid & 1;
    const u32 dstB = 6144u + (u32)(rowB * PITCH + chB * 16);

    auto LOADC = [&](int i, int s) {
        const int k = i >> 3, c0 = (i & 7) << 5;
        const int ky = k / 3, kx = k - (k / 3) * 3;
        const int sy = py + ky - 1, sx = px + kx - 1;
        const bool v = ((unsigned)sy < HH) & ((unsigned)sx < WW);
        const int ga0 = ((pixrowbase + sy * WW + sx) << 8) + chA * 8;
        const int gb0 = ((k * CH + octile + rowB) << 8) + chB * 8;
#pragma unroll
        for (int h = 0; h < 2; ++h) {
            const int ch = c0 + h * 16;
            const u32 base = sb + s * C1_ST + h * C1_HALF;
            cpa16(base + dstA, v ? (const void*)(g_xh + ga0 + ch) : (const void*)g_xh, v ? 16u : 0u);
            cpa16ca(base + dstB, g_w1h + gb0 + ch);
        }
    };

    const int wm = wid >> 2, wn = wid & 3;
    const u32 aoff = (u32)((wm * 64 + (lane & 15)) * PITCH + (lane >> 4) * 16);
    const u32 boff = 6144u + (u32)((wn * 32 + ((lane >> 4) << 3) + (lane & 7)) * PITCH +
                                   ((lane >> 3) & 1) * 16);
    float acc[4][4][4];
#pragma unroll
    for (int a = 0; a < 4; ++a)
#pragma unroll
        for (int b = 0; b < 4; ++b)
#pragma unroll
            for (int c = 0; c < 4; ++c) acc[a][b][c] = 0.f;

    auto COMP = [&](int s) {
#pragma unroll
        for (int h = 0; h < 2; ++h) {
            const u32 sub = sb + s * C1_ST + h * C1_HALF;
            const u32 ab = sub + aoff;
            const u32 bbx = sub + boff;
            u32 bh0[4], bh1[4];
            ldm4(bbx, bh0); ldm4(bbx + 768, bh1);
            u32 ah[2][4];
            ldm4(ab, ah[0]);
#pragma unroll
            for (int mt = 0; mt < 4; ++mt) {
                const int cur = mt & 1, nxt = cur ^ 1;
                if (mt < 3) ldm4(ab + (mt + 1) * 768, ah[nxt]);
#pragma unroll
                for (int nt = 0; nt < 4; ++nt) {
                    u32* bq = (nt < 2) ? bh0 : bh1; const int hh = (nt & 1) * 2;
                    mma_f16(acc[mt][nt], ah[cur], bq[hh], bq[hh + 1]);
                }
            }
        }
    };

    LOADC(0, 0); CPCOMMIT();
    LOADC(1, 1); CPCOMMIT();
    for (int i = 0; i < NIT32; ++i) {
        CPWAIT1();                 // group i complete
        __syncthreads();
        if (i + 2 < NIT32) LOADC(i + 2, (i + 2) % 3);  // stage (i-1)%3: reads done pre-sync
        CPCOMMIT();
        COMP(i % 3);
    }

    const int g = lane >> 2, t2 = (lane & 3) * 2;
#pragma unroll
    for (int mt = 0; mt < 4; ++mt) {
        const int pr = pixbase + wm * 64 + mt * 16 + g;
#pragma unroll
        for (int nt = 0; nt < 4; ++nt) {
            const int oc = octile + wn * 32 + nt * 8 + t2;
            const float i0 = invbet[oc], i1 = invbet[oc + 1];
            const float e0 = invbet[256 + oc], e1 = invbet[256 + oc + 1];
            const float v00 = fmaxf(fmaf(acc[mt][nt][0], i0, e0), 0.f);
            const float v01 = fmaxf(fmaf(acc[mt][nt][1], i1, e1), 0.f);
            const float v10 = fmaxf(fmaf(acc[mt][nt][2], i0, e0), 0.f);
            const float v11 = fmaxf(fmaf(acc[mt][nt][3], i1, e1), 0.f);
            __half2 th;
            th.x = __float2half(v00); th.y = __float2half(v01);
            *(__half2*)(g_o1h + pr * CH + oc) = th;
            th.x = __float2half(v10); th.y = __float2half(v11);
            *(__half2*)(g_o1h + (pr + 8) * CH + oc) = th;
        }
    }
}

// ================= offset conv: 128px x 32oc, BK=32, 4-stage =================
// half (7680): A 0 (6144), B 6144 (1536); stage = 15360
#define OF_HALF 7680
#define OF_ST   15360
#define OF_OB   61440
#define OF_SZ   61568

__global__ __launch_bounds__(256, 2)
void convoff_mma(const float* __restrict__ offb) {
    extern __shared__ __align__(16) char S[];
    const int tid = threadIdx.x, lane = tid & 31, wid = tid >> 5;
    const int pixbase = blockIdx.x * 128;
    const u32 sb = smem_u32(S);
    float* obs = (float*)(S + OF_OB);
    if (tid < 32) obs[tid] = (tid < 18) ? offb[tid] : 0.f;

    const int rowA = tid >> 1, chA = tid & 1;
    const int gp = pixbase + rowA;
    const int bIdx = gp / HWSZ, rem = gp - bIdx * HWSZ;
    const int py = rem / WW, px = rem - (rem / WW) * WW;
    const int pixrowbase = bIdx * HWSZ;
    const u32 dstA = (u32)(rowA * PITCH + chA * 16);
    const int rowB = (tid >> 1) & 31, chB = tid & 1;   // valid for tid<64
    const u32 dstB = 6144u + (u32)(rowB * PITCH + chB * 16);

    auto LOADC = [&](int i, int s) {
        const int k = i >> 3, c0 = (i & 7) << 5;
        const int ky = k / 3, kx = k - (k / 3) * 3;
        const int sy = py + ky - 1, sx = px + kx - 1;
        const bool v = ((unsigned)sy < HH) & ((unsigned)sx < WW);
        const int ga0 = ((pixrowbase + sy * WW + sx) << 8) + chA * 8;
#pragma unroll
        for (int h = 0; h < 2; ++h) {
            const int ch = c0 + h * 16;
            const u32 base = sb + s * OF_ST + h * OF_HALF;
            cpa16(base + dstA, v ? (const void*)(g_o1h + ga0 + ch) : (const void*)g_o1h, v ? 16u : 0u);
            if (tid < 64) {
                const int gb = ((k * 32 + rowB) << 8) + ch + chB * 8;
                cpa16ca(base + dstB, g_woh + gb);
            }
        }
    };

    const int wm = wid >> 1, wn = wid & 1;
    const u32 aoff = (u32)((wm * 32 + (lane & 15)) * PITCH + (lane >> 4) * 16);
    const u32 boff = 6144u + (u32)((wn * 16 + ((lane >> 4) << 3) + (lane & 7)) * PITCH +
                                   ((lane >> 3) & 1) * 16);
    float acc[2][2][4];
#pragma unroll
    for (int a = 0; a < 2; ++a)
#pragma unroll
        for (int b = 0; b < 2; ++b)
#pragma unroll
            for (int c = 0; c < 4; ++c) acc[a][b][c] = 0.f;

    auto COMP = [&](int s) {
#pragma unroll
        for (int h = 0; h < 2; ++h) {
            const u32 sub = sb + s * OF_ST + h * OF_HALF;
            const u32 ab = sub + aoff;
            const u32 bbx = sub + boff;
            u32 bh[4];
            ldm4(bbx, bh);
            u32 ah[2][4];
            ldm4(ab, ah[0]);
            ldm4(ab + 768, ah[1]);
#pragma unroll
            for (int mt = 0; mt < 2; ++mt)
#pragma unroll
                for (int nt = 0; nt < 2; ++nt)
                    mma_f16(acc[mt][nt], ah[mt], bh[nt * 2], bh[nt * 2 + 1]);
        }
    };

    LOADC(0, 0); CPCOMMIT();
    LOADC(1, 1); CPCOMMIT();
    LOADC(2, 2); CPCOMMIT();
    for (int i = 0; i < NIT32; ++i) {
        CPWAIT2();
        __syncthreads();
        if (i + 3 < NIT32) LOADC(i + 3, (i + 3) & 3);
        CPCOMMIT();
        COMP(i & 3);
    }

    const int g = lane >> 2, t2 = (lane & 3) * 2;
#pragma unroll
    for (int mt = 0; mt < 2; ++mt) {
        const int pr = pixbase + wm * 32 + mt * 16 + g;
#pragma unroll
        for (int nt = 0; nt < 2; ++nt) {
            const int oc = wn * 16 + nt * 8 + t2;
            if (oc < 18) {
                g_offs[pr * 18 + oc] = acc[mt][nt][0] + obs[oc];
                g_offs[(pr + 8) * 18 + oc] = acc[mt][nt][2] + obs[oc];
            }
            if (oc + 1 < 18) {
                g_offs[pr * 18 + oc + 1] = acc[mt][nt][1] + obs[oc + 1];
                g_offs[(pr + 8) * 18 + oc + 1] = acc[mt][nt][3] + obs[oc + 1];
            }
        }
    }
}

// ================= deformable conv: 64px x 128oc per CTA (R12 config) =================
// A: 2 stages x 3072; B: 4 stages x 6144 at 6144; fp16 gather; B via .cg
#define DF_AST 3072
#define DF_B0  6144
#define DF_IB  30720
#define DF_CW  32768
#define DF_PK  41984
#define DF_SZ  44544
#define NITER  144

__global__ __launch_bounds__(128, 3)
void deform_mma(const float* __restrict__ bg, const float* __restrict__ bb_,
                const float* __restrict__ bm, const float* __restrict__ bv,
                const float* __restrict__ resid, float* __restrict__ out) {
    extern __shared__ __align__(16) char S[];
    const int tid = threadIdx.x, lane = tid & 31, wid = tid >> 5;
    const int pixbase = blockIdx.x * 64, octile = blockIdx.y * 128;
    const u32 sb = smem_u32(S);
    float*  invbet = (float*)(S + DF_IB);
    float4* cwS = (float4*)(S + DF_CW);
    int*    cpkS = (int*)(S + DF_PK);
    {
        const float iv0 = bg[tid] * rsqrtf(bv[tid] + EPSBN);
        invbet[tid] = iv0;
        invbet[256 + tid] = bb_[tid] - bm[tid] * iv0;
        const float iv1 = bg[tid + 128] * rsqrtf(bv[tid + 128] + EPSBN);
        invbet[tid + 128] = iv1;
        invbet[256 + tid + 128] = bb_[tid + 128] - bm[tid + 128] * iv1;
    }
    for (int idx = tid; idx < 64 * 9; idx += 128) {
        const int p = idx / 9, k = idx - (idx / 9) * 9;
        const int gpq = pixbase + p;
        const int b = gpq / HWSZ, rm = gpq - b * HWSZ;
        const int yy = rm / WW, xx = rm - (rm / WW) * WW;
        const float oy = g_offs[gpq * 18 + k];
        const float ox = g_offs[gpq * 18 + 9 + k];
        const float ys = (float)(yy + k / 3 - 1) + oy;
        const float xs = (float)(xx + (k - (k / 3) * 3) - 1) + ox;
        const float yf = floorf(ys), xf = floorf(xs);
        const float ty = ys - yf, tx = xs - xf;
        const int iy0 = (int)yf, ix0 = (int)xf;
        const int iy1 = iy0 + 1, ix1 = ix0 + 1;
        const float vy0 = ((unsigned)iy0 < HH) ? 1.f : 0.f;
        const float vy1 = ((unsigned)iy1 < HH) ? 1.f : 0.f;
        const float vx0 = ((unsigned)ix0 < WW) ? 1.f : 0.f;
        const float vx1 = ((unsigned)ix1 < WW) ? 1.f : 0.f;
        cwS[idx] = make_float4((1.f - ty) * (1.f - tx) * vy0 * vx0,
                               (1.f - ty) * tx * vy0 * vx1,
                               ty * (1.f - tx) * vy1 * vx0,
                               ty * tx * vy1 * vx1);
        const int cy0 = min(max(iy0, 0), HH - 1), cy1 = min(max(iy1, 0), HH - 1);
        const int cx0 = min(max(ix0, 0), WW - 1), cx1 = min(max(ix1, 0), WW - 1);
        cpkS[idx] = cy0 | (cx0 << 8) | (cy1 << 16) | (cx1 << 24);
    }
    __syncthreads();

    const int rowA = tid >> 1, chA = tid & 1;
    const int gp = pixbase + rowA;
    const int pixrowbase = (gp / HWSZ) * HWSZ;
    const u32 dstA = (u32)(rowA * PITCH + chA * 16);
    const int rowB = tid >> 1, chB = tid & 1;
    const u32 dstB = (u32)(rowB * PITCH + chB * 16);

    uint4 cr[4];     // fp16 gather: 8 ch x 4 corners
    float4 wreg;

    auto LDGA = [&](int i) {
        const int k = i >> 4, c0 = (i & 15) << 4;
        wreg = cwS[rowA * 9 + k];
        const int pk = cpkS[rowA * 9 + k];
        const int cc = c0 + chA * 8;
        const int r00 = ((pixrowbase + (pk & 255) * WW + ((pk >> 8) & 255)) << 8) + cc;
        const int r01 = ((pixrowbase + (pk & 255) * WW + ((pk >> 24) & 255)) << 8) + cc;
        const int r10 = ((pixrowbase + ((pk >> 16) & 255) * WW + ((pk >> 8) & 255)) << 8) + cc;
        const int r11 = ((pixrowbase + ((pk >> 16) & 255) * WW + ((pk >> 24) & 255)) << 8) + cc;
        cr[0] = *(const uint4*)(g_o1h + r00);
        cr[1] = *(const uint4*)(g_o1h + r01);
        cr[2] = *(const uint4*)(g_o1h + r10);
        cr[3] = *(const uint4*)(g_o1h + r11);
    };
    auto STSA = [&](int s) {
        __align__(16) __half hh[8];
        const __half2* c00 = (const __half2*)&cr[0];
        const __half2* c01 = (const __half2*)&cr[1];
        const __half2* c10 = (const __half2*)&cr[2];
        const __half2* c11 = (const __half2*)&cr[3];
#pragma unroll
        for (int q = 0; q < 4; ++q) {
            const float2 s00 = __half22float2(c00[q]);
            const float2 s01 = __half22float2(c01[q]);
            const float2 s10 = __half22float2(c10[q]);
            const float2 s11 = __half22float2(c11[q]);
            float vx, vy;
            vx = fmaf(wreg.x, s00.x, fmaf(wreg.y, s01.x, fmaf(wreg.z, s10.x, wreg.w * s11.x)));
            vy = fmaf(wreg.x, s00.y, fmaf(wreg.y, s01.y, fmaf(wreg.z, s10.y, wreg.w * s11.y)));
            hh[q * 2 + 0] = __float2half(vx);
            hh[q * 2 + 1] = __float2half(vy);
        }
        *(uint4*)(S + s * DF_AST + dstA) = *(uint4*)hh;
    };
    auto CPB = [&](int i, int s) {
        const int k = i >> 4, c0 = (i & 15) << 4;
        const int gb0 = ((k * CH + octile + rowB) << 8) + c0 + chB * 8;
        const int gb1 = gb0 + (64 << 8);
        const u32 base = sb + DF_B0 + s * 6144;
        cpa16(base + dstB,        g_w2h + gb0, 16u);
        cpa16(base + 3072 + dstB, g_w2h + gb1, 16u);
    };

    const int wn = wid & 3;
    const u32 aoff = (u32)((lane & 15) * PITCH + (lane >> 4) * 16);
    const u32 boff = (u32)((wn * 32 + ((lane >> 4) << 3) + (lane & 7)) * PITCH +
                           ((lane >> 3) & 1) * 16);
    float acc[4][4][4];
#pragma unroll
    for (int a = 0; a < 4; ++a)
#pragma unroll
        for (int b = 0; b < 4; ++b)
#pragma unroll
            for (int c = 0; c < 4; ++c) acc[a][b][c] = 0.f;

    auto COMP = [&](int sa, int sbst) {
        const u32 ab = sb + sa * DF_AST + aoff;
        const u32 bbx = sb + DF_B0 + sbst * 6144 + boff;
        u32 bh0[4], bh1[4];
        ldm4(bbx, bh0); ldm4(bbx + 768, bh1);
        u32 ah[2][4];
        ldm4(ab, ah[0]);
#pragma unroll
        for (int mt = 0; mt < 4; ++mt) {
            const int cur = mt & 1, nxt = cur ^ 1;
            if (mt < 3) ldm4(ab + (mt + 1) * 768, ah[nxt]);
#pragma unroll
            for (int nt = 0; nt < 4; ++nt) {
                u32* bq = (nt < 2) ? bh0 : bh1; const int h = (nt & 1) * 2;
                mma_f16(acc[mt][nt], ah[cur], bq[h], bq[h + 1]);
            }
        }
    };

    LDGA(0); STSA(0);
    CPB(0, 0); CPCOMMIT();
    CPB(1, 1); CPCOMMIT();
    CPB(2, 2); CPCOMMIT();
    __syncthreads();

    for (int i = 0; i < NITER; ++i) {
        CPWAIT2();                 // B group i arrived
        __syncthreads();           // STSA(i) + B(i) visible
        if (i + 3 < NITER) CPB(i + 3, (i + 3) & 3);   // stage (i-1)&3
        CPCOMMIT();
        if (i + 1 < NITER) LDGA(i + 1);
        COMP(i & 1, i & 3);
        if (i + 1 < NITER) STSA((i + 1) & 1);
    }

    const int g = lane >> 2, t2 = (lane & 3) * 2;
#pragma unroll
    for (int mt = 0; mt < 4; ++mt) {
        const int pr0 = pixbase + mt * 16 + g;
        const int pr1 = pr0 + 8;
        const int b0 = pr0 / HWSZ, rm0 = pr0 - b0 * HWSZ;
        const int b1 = pr1 / HWSZ, rm1 = pr1 - b1 * HWSZ;
        const int base0 = b0 * (CH * HWSZ) + rm0;
        const int base1 = b1 * (CH * HWSZ) + rm1;
#pragma unroll
        for (int nt = 0; nt < 4; ++nt) {
            const int oc = octile + wn * 32 + nt * 8 + t2;
            const float i0 = invbet[oc], i1 = invbet[oc + 1];
            const float e0 = invbet[256 + oc], e1 = invbet[256 + oc + 1];
            const int a00 = base0 + oc * HWSZ, a01 = a00 + HWSZ;
            const int a10 = base1 + oc * HWSZ, a11 = a10 + HWSZ;
            out[a00] = fmaxf(fmaf(acc[mt][nt][0], i0, e0) + resid[a00], 0.f);
            out[a01] = fmaxf(fmaf(acc[mt][nt][1], i1, e1) + resid[a01], 0.f);
            out[a10] = fmaxf(fmaf(acc[mt][nt][2], i0, e0) + resid[a10], 0.f);
            out[a11] = fmaxf(fmaf(acc[mt][nt][3], i1, e1) + resid[a11], 0.f);
        }
    }
}

// ---------------- launch ----------------
extern "C" void kernel_launch(void* const* d_in, const int* in_sizes, int n_in,
                              void* d_out, int out_size) {
    const float* x    = (const float*)d_in[0];
    const float* w1   = (const float*)d_in[1];
    const float* bn1g = (const float*)d_in[2];
    const float* bn1b = (const float*)d_in[3];
    const float* bn1m = (const float*)d_in[4];
    const float* bn1v = (const float*)d_in[5];
    const float* woff = (const float*)d_in[6];
    const float* offb = (const float*)d_in[7];
    const float* w2   = (const float*)d_in[8];
    const float* bn2g = (const float*)d_in[9];
    const float* bn2b = (const float*)d_in[10];
    const float* bn2m = (const float*)d_in[11];
    const float* bn2v = (const float*)d_in[12];
    float* out = (float*)d_out;

    cudaFuncSetAttribute(conv1_mma,   cudaFuncAttributeMaxDynamicSharedMemorySize, C1_SZ);
    cudaFuncSetAttribute(convoff_mma, cudaFuncAttributeMaxDynamicSharedMemorySize, OF_SZ);
    cudaFuncSetAttribute(deform_mma,  cudaFuncAttributeMaxDynamicSharedMemorySize, DF_SZ);

    prep_x<<<dim3(98, 8, BATCH), dim3(32, 8)>>>(x);
    prep_w<<<2304, 256>>>(w1, 0);
    prep_woff<<<288, 256>>>(woff);
    conv1_mma<<<dim3(196, 2), 256, C1_SZ>>>(bn1g, bn1b, bn1m, bn1v);
    prep_w<<<2304, 256>>>(w2, 1);
    convoff_mma<<<196, 256, OF_SZ>>>(offb);
    deform_mma<<<dim3(392, 2), 128, DF_SZ>>>(bn2g, bn2b, bn2m, bn2v, x, out);
}